// round 10
// baseline (speedup 1.0000x reference)
#include <cuda_runtime.h>
#include <cuda.h>
#include <cstdint>

// ============================================================
// out = x @ (W + s * kron(A,B) * 2)^T
// out[m,i] = (x@W^T)[m,i] + 2*s*B[i%16]*(x@A^T)[m, i/16]
//
// Round 10: fp16 MMA (m16n8k16, fp32 acc) — same 10-bit mantissa as
//   tf32, 2x MAC/instr. W fp32 converted in-kernel by 4 warp-specialized
//   converter warps (LDG.64 -> cvt.rn.f16x2 -> STS.64 in fragment order).
//   x pre-packed fp16 A-fragments by prep_x, fed via cp.async.bulk.
//   16 consumer warps (4/SMSP), warp tile 64x32, 5 stages x 24KB.
//   136 CTAs = (32 W-tiles + 2 A-tiles) x 4 k-quarters, M_CTA=256.
// ============================================================

__device__ __forceinline__ uint32_t smem_u32(const void* p) {
    uint32_t a;
    asm("{ .reg .u64 t; cvta.to.shared.u64 t, %1; cvt.u32.u64 %0, t; }" : "=r"(a) : "l"(p));
    return a;
}

#define MBARRIER_INIT(addr, cnt) \
    asm volatile("mbarrier.init.shared.b64 [%0], %1;" :: "r"((uint32_t)(addr)), "r"((uint32_t)(cnt)) : "memory")

#define MBARRIER_EXPECT_TX(addr, bytes) \
    asm volatile("mbarrier.arrive.expect_tx.shared.b64 _, [%0], %1;" :: "r"((uint32_t)(addr)), "r"((uint32_t)(bytes)) : "memory")

#define MBARRIER_ARRIVE(addr) \
    asm volatile("mbarrier.arrive.shared.b64 _, [%0];" :: "r"((uint32_t)(addr)) : "memory")

#define MBARRIER_WAIT_PARITY(mbar, parity) do {                                      \
    uint32_t _m = (uint32_t)(mbar); uint32_t _p = (uint32_t)(parity);                \
    asm volatile(                                                                    \
        "{\n\t.reg .pred P1;\n\t"                                                    \
        "WAIT_LOOP_%=:\n\t"                                                          \
        "mbarrier.try_wait.parity.shared.b64 P1, [%0], %1;\n\t"                      \
        "@P1 bra.uni WAIT_DONE_%=;\n\t"                                              \
        "bra.uni WAIT_LOOP_%=;\n\t"                                                  \
        "WAIT_DONE_%=:\n\t}"                                                         \
        :: "r"(_m), "r"(_p) : "memory");                                             \
} while (0)

#define BULK_LOAD(smem_addr, gptr, bytes, mbar) \
    asm volatile("cp.async.bulk.shared::cluster.global.mbarrier::complete_tx::bytes " \
                 "[%0], [%1], %2, [%3];" \
        :: "r"((uint32_t)(smem_addr)), "l"(gptr), "r"((uint32_t)(bytes)), "r"((uint32_t)(mbar)) : "memory")

__device__ __forceinline__ void lds64(uint32_t a, uint32_t& r0, uint32_t& r1) {
    asm volatile("ld.shared.v2.b32 {%0,%1}, [%2];" : "=r"(r0), "=r"(r1) : "r"(a));
}
__device__ __forceinline__ void lds128(uint32_t a, uint32_t& r0, uint32_t& r1, uint32_t& r2, uint32_t& r3) {
    asm volatile("ld.shared.v4.b32 {%0,%1,%2,%3}, [%4];"
                 : "=r"(r0), "=r"(r1), "=r"(r2), "=r"(r3) : "r"(a));
}
__device__ __forceinline__ void sts64(uint32_t a, uint32_t r0, uint32_t r1) {
    asm volatile("st.shared.v2.b32 [%0], {%1,%2};" :: "r"(a), "r"(r0), "r"(r1) : "memory");
}
__device__ __forceinline__ float2 ldg64(const float* p) {
    float2 v;
    asm volatile("ld.global.nc.v2.f32 {%0,%1}, [%2];" : "=f"(v.x), "=f"(v.y) : "l"(p));
    return v;
}
// pack: result = {lo in low 16 bits, hi in high 16 bits}
__device__ __forceinline__ uint32_t f2h2(float hi, float lo) {
    uint32_t r;
    asm("cvt.rn.f16x2.f32 %0, %1, %2;" : "=r"(r) : "f"(hi), "f"(lo));
    return r;
}
__device__ __forceinline__ void mma_f16(float* d, uint32_t a0, uint32_t a1, uint32_t a2, uint32_t a3,
                                        uint32_t b0, uint32_t b1) {
    asm volatile(
        "mma.sync.aligned.m16n8k16.row.col.f32.f16.f16.f32 "
        "{%0,%1,%2,%3}, {%4,%5,%6,%7}, {%8,%9}, {%0,%1,%2,%3};"
        : "+f"(d[0]), "+f"(d[1]), "+f"(d[2]), "+f"(d[3])
        : "r"(a0), "r"(a1), "r"(a2), "r"(a3), "r"(b0), "r"(b1));
}

// ---------------- config ----------------
static constexpr int KQ          = 2048;          // K per CTA (quarter)
static constexpr int KC          = 32;            // K per pipeline chunk (2 k16-steps)
static constexpr int NK          = KQ / KC;       // 64 chunks
static constexpr int STAGES      = 5;
static constexpr int W_STAGE     = 16384;         // 2048 frag-slots x 8B fp16
static constexpr int X_STAGE     = 8192;          // 512 frag-slots x 16B fp16
static constexpr int STAGE_BYTES = W_STAGE + X_STAGE;  // 24 KB
static constexpr int SMEM_HDR    = 1024;
static constexpr int SMEM_BYTES  = SMEM_HDR + STAGES * STAGE_BYTES;  // 123904
static constexpr int OFF_FULL    = 0;
static constexpr int OFF_EMPTY   = 128;
static constexpr int NCONS       = 16;            // consumer warps (4/SMSP)
static constexpr int NCVT        = 4;             // converter warps

__device__ uint4  g_xpack[131072];         // x as fp16 A-fragments (2MB)
__device__ float  g_P[3][128 * 8192];      // k-quarter partials 1..3 of x@W^T
__device__ float  g_Y2[4][128 * 512];      // k-quarter partials of x@A^T

__global__ void dummy_k() {}

// ---------------- prep: x -> fp16 A-fragment order ----------------
// group g in chunk kc: lg=g&31, mb=(g>>5)&7, s=g>>8
//   m = mb*16 + lg/4, c = s*16 + (lg&3)*2  (k within chunk)
// uint4 = {pack(x[m][c],x[m][c+1]), pack(x[m+8][c],..), pack(x[m][c+8],..), pack(x[m+8][c+8],..)}
__global__ void __launch_bounds__(256)
prep_x(const float* __restrict__ x)
{
    __shared__ float sm[128][33];
    const int kc   = blockIdx.x;        // 0..255
    const int tid  = threadIdx.x;
    const int w    = tid >> 5;
    const int lane = tid & 31;
    const int k0   = kc * 32;

    #pragma unroll
    for (int i = 0; i < 16; i++) {
        int m = w * 16 + i;
        sm[m][lane] = x[(size_t)m * 8192 + k0 + lane];
    }
    __syncthreads();

    uint4* dst = g_xpack + (size_t)kc * 512;
    #pragma unroll
    for (int pass = 0; pass < 2; pass++) {
        int g  = tid + pass * 256;
        int lg = g & 31, mb = (g >> 5) & 7, s = g >> 8;
        int m = mb * 16 + (lg >> 2);
        int c = s * 16 + (lg & 3) * 2;
        uint4 v;
        v.x = f2h2(sm[m][c + 1],     sm[m][c]);
        v.y = f2h2(sm[m + 8][c + 1], sm[m + 8][c]);
        v.z = f2h2(sm[m][c + 9],     sm[m][c + 8]);
        v.w = f2h2(sm[m + 8][c + 9], sm[m + 8][c + 8]);
        dst[g] = v;
    }
}

// ---------------- GEMM kernel ----------------
// bid<128: W tile (bid>>2)*256 rows, kq=bid&3.  bid>=128: A tile ((bid-128)>>2)*256, kq.
// warps 0..15 consumers (wm=wid&1: 64 x-rows; nw=wid>>1: 32 W-rows),
// warps 16..19 converters (LDG fp32 W -> fp16 fragment STS), cvt warp0 lane0 also feeds x.
__global__ void __launch_bounds__(640, 1)
lokr_gemm(const float* __restrict__ Wp, const float* __restrict__ Ap,
          float* __restrict__ d_out)
{
    extern __shared__ char smem[];
    const uint32_t sb = smem_u32(smem);
    const int tid  = threadIdx.x;
    const int wid  = tid >> 5;
    const int lane = tid & 31;

    const bool isA = (blockIdx.x >= 128);
    const int  b   = isA ? (blockIdx.x - 128) : blockIdx.x;
    const int  kq  = b & 3;
    const int  row0 = (b >> 2) * 256;

    if (tid == 0) {
        #pragma unroll
        for (int s = 0; s < STAGES; s++) {
            MBARRIER_INIT(sb + OFF_FULL  + s * 8, NCVT * 32 + 1);  // 128 cvt lanes + expect_tx arrive
            MBARRIER_INIT(sb + OFF_EMPTY + s * 8, NCONS);
        }
    }
    __syncthreads();

    if (wid >= NCONS) {
        // ---------------- converters ----------------
        const int ct = (wid - NCONS) * 32 + lane;   // 0..127
        const float* srcp = isA ? Ap : Wp;
        const float* gbase = srcp + (size_t)row0 * 8192 + kq * KQ;
        const char*  xsrc  = reinterpret_cast<const char*>(g_xpack) + (size_t)kq * 64 * 8192;

        int es = 0, eph = 1;
        for (int c = 0; c < NK; c++) {
            MBARRIER_WAIT_PARITY(sb + OFF_EMPTY + es * 8, eph);
            uint32_t full = sb + OFF_FULL + es * 8;
            uint32_t st   = sb + SMEM_HDR + es * STAGE_BYTES;
            if (ct == 0) {
                MBARRIER_EXPECT_TX(full, X_STAGE);
                BULK_LOAD(st + W_STAGE, xsrc + (size_t)c * X_STAGE, X_STAGE, full);
            }
            const float* gw = gbase + c * KC;
            #pragma unroll 4
            for (int i = 0; i < 16; i++) {
                int g  = i * 128 + ct;             // 0..2047
                int t  = g & 31;
                int jj = (g >> 5) & 31;
                int s  = g >> 10;
                int n  = jj * 8 + (t >> 2);
                int kk = s * 16 + (t & 3) * 2;
                const float* p = gw + (size_t)n * 8192 + kk;
                float2 w0 = ldg64(p);
                float2 w1 = ldg64(p + 8);
                sts64(st + (uint32_t)g * 8, f2h2(w0.y, w0.x), f2h2(w1.y, w1.x));
            }
            MBARRIER_ARRIVE(full);                 // per-lane arrive releases own STS
            if (++es == STAGES) { es = 0; eph ^= 1; }
        }
    } else {
        // ---------------- consumers ----------------
        float acc[4][4][4] = {};             // [i: x m16-block][j: W n8-block][frag]
        const int wm = wid & 1;              // x-row half (64 rows)
        const int nj = (wid >> 1) * 4;       // first n8-block (4 blocks = 32 W-rows)
        const int r8 = lane >> 2;
        const int cc = lane & 3;
        const uint32_t wfb = (uint32_t)lane * 8;
        const uint32_t xfb = (uint32_t)W_STAGE + (uint32_t)lane * 16;

        int cs = 0, cph = 0;
        for (int c = 0; c < NK; c++) {
            MBARRIER_WAIT_PARITY(sb + OFF_FULL + cs * 8, cph);
            const uint32_t stg = sb + SMEM_HDR + (uint32_t)cs * STAGE_BYTES;

            #pragma unroll
            for (int s = 0; s < 2; s++) {
                uint32_t ub[4][2];
                #pragma unroll
                for (int j = 0; j < 4; j++)
                    lds64(stg + wfb + (uint32_t)((s * 32 + nj + j) << 8), ub[j][0], ub[j][1]);
                #pragma unroll
                for (int i = 0; i < 4; i++) {
                    uint32_t a0, a1, a2, a3;
                    lds128(stg + xfb + (uint32_t)((s * 8 + wm * 4 + i) << 9), a0, a1, a2, a3);
                    #pragma unroll
                    for (int j = 0; j < 4; j++)
                        mma_f16(acc[i][j], a0, a1, a2, a3, ub[j][0], ub[j][1]);
                }
            }

            __syncwarp();
            if (lane == 0) MBARRIER_ARRIVE(sb + OFF_EMPTY + cs * 8);
            if (++cs == STAGES) { cs = 0; cph ^= 1; }
        }

        // ---------------- epilogue ----------------
        float* ob;
        int stride;
        if (isA) { ob = g_Y2[kq]; stride = 512; }
        else     { ob = kq ? g_P[kq - 1] : d_out; stride = 8192; }
        #pragma unroll
        for (int i = 0; i < 4; i++) {
            #pragma unroll
            for (int j = 0; j < 4; j++) {
                int m = wm * 64 + 16 * i + r8;
                int n = row0 + nj * 8 + 8 * j + 2 * cc;
                *reinterpret_cast<float2*>(&ob[(size_t)m * stride + n]) =
                    make_float2(acc[i][j][0], acc[i][j][1]);
                *reinterpret_cast<float2*>(&ob[(size_t)(m + 8) * stride + n]) =
                    make_float2(acc[i][j][2], acc[i][j][3]);
            }
        }
    }
}

// ---------------- combine kernel ----------------
__global__ void __launch_bounds__(256)
lokr_combine(const float* __restrict__ lokrB, const float* __restrict__ scalar,
             float* __restrict__ out)
{
    int idx = blockIdx.x * blockDim.x + threadIdx.x;   // float4 id, 0..262143
    int m = idx >> 11;
    int r = idx & 2047;
    int yi = m * 512 + (r >> 2);
    float coef = 2.0f * scalar[0] *
        (g_Y2[0][yi] + g_Y2[1][yi] + g_Y2[2][yi] + g_Y2[3][yi]);

    float4 bv = reinterpret_cast<const float4*>(lokrB)[r & 3];
    float4 o  = reinterpret_cast<float4*>(out)[idx];
    float4 a  = reinterpret_cast<const float4*>(g_P[0])[idx];
    float4 b  = reinterpret_cast<const float4*>(g_P[1])[idx];
    float4 c  = reinterpret_cast<const float4*>(g_P[2])[idx];
    o.x += a.x + b.x + c.x + coef * bv.x;
    o.y += a.y + b.y + c.y + coef * bv.y;
    o.z += a.z + b.z + c.z + coef * bv.z;
    o.w += a.w + b.w + c.w + coef * bv.w;
    reinterpret_cast<float4*>(out)[idx] = o;
}

// ---------------- host ----------------
extern "C" void kernel_launch(void* const* d_in, const int* in_sizes, int n_in,
                              void* d_out, int out_size)
{
    (void)in_sizes; (void)n_in; (void)out_size;
    const float* x  = (const float*)d_in[0];
    const float* W  = (const float*)d_in[1];
    const float* A  = (const float*)d_in[2];
    const float* B  = (const float*)d_in[3];
    const float* sc = (const float*)d_in[4];

    cudaFuncSetAttribute(lokr_gemm, cudaFuncAttributeMaxDynamicSharedMemorySize, SMEM_BYTES);

    // Keep ncu (-s 5 -c 1) landing on the GEMM.
    dummy_k<<<1, 1>>>();
    dummy_k<<<1, 1>>>();
    prep_x<<<256, 256>>>(x);
    lokr_gemm<<<136, 640, SMEM_BYTES>>>(W, A, (float*)d_out);
    lokr_combine<<<1024, 256>>>(B, sc, (float*)d_out);
}

// round 11
// speedup vs baseline: 1.9840x; 1.9840x over previous
#include <cuda_runtime.h>
#include <cuda.h>
#include <cstdint>

// ============================================================
// out = x @ (W + s * kron(A,B) * 2)^T
// out[m,i] = (x@W^T)[m,i] + 2*s*B[i%16]*(x@A^T)[m, i/16]
//
// Round 11: fp16 MMA with the PROVEN TMA feed.
//   - W: TMA SW128 fp32 -> smem; consumers LDS.64 fp32 pairs ->
//     cvt.rn.f16x2 -> mma.m16n8k16.f16.f32acc (half the MMA count of r9).
//   - x: prepacked fp16 A-fragments (r10 layout, validated), 8KB/chunk bulk.
//   - 136 CTAs = (32 W + 2 A tiles) x 4 k-quarters, M_CTA=256,
//     16 consumer warps (4/SMSP) + 1 producer, 4 stages x 40KB.
// ============================================================

__device__ __forceinline__ uint32_t smem_u32(const void* p) {
    uint32_t a;
    asm("{ .reg .u64 t; cvta.to.shared.u64 t, %1; cvt.u32.u64 %0, t; }" : "=r"(a) : "l"(p));
    return a;
}

#define MBARRIER_INIT(addr, cnt) \
    asm volatile("mbarrier.init.shared.b64 [%0], %1;" :: "r"((uint32_t)(addr)), "r"((uint32_t)(cnt)) : "memory")

#define MBARRIER_EXPECT_TX(addr, bytes) \
    asm volatile("mbarrier.arrive.expect_tx.shared.b64 _, [%0], %1;" :: "r"((uint32_t)(addr)), "r"((uint32_t)(bytes)) : "memory")

#define MBARRIER_ARRIVE(addr) \
    asm volatile("mbarrier.arrive.shared.b64 _, [%0];" :: "r"((uint32_t)(addr)) : "memory")

#define MBARRIER_WAIT_PARITY(mbar, parity) do {                                      \
    uint32_t _m = (uint32_t)(mbar); uint32_t _p = (uint32_t)(parity);                \
    asm volatile(                                                                    \
        "{\n\t.reg .pred P1;\n\t"                                                    \
        "WAIT_LOOP_%=:\n\t"                                                          \
        "mbarrier.try_wait.parity.shared.b64 P1, [%0], %1;\n\t"                      \
        "@P1 bra.uni WAIT_DONE_%=;\n\t"                                              \
        "bra.uni WAIT_LOOP_%=;\n\t"                                                  \
        "WAIT_DONE_%=:\n\t}"                                                         \
        :: "r"(_m), "r"(_p) : "memory");                                             \
} while (0)

#define TMA_LOAD_2D(smem_addr, map, cx, cy, mbar) \
    asm volatile("cp.async.bulk.tensor.2d.shared::cluster.global.tile.mbarrier::complete_tx::bytes " \
                 "[%0], [%1, {%2, %3}], [%4];" \
        :: "r"((uint32_t)(smem_addr)), "l"(map), "r"((int)(cx)), "r"((int)(cy)), "r"((uint32_t)(mbar)) : "memory")

#define BULK_LOAD(smem_addr, gptr, bytes, mbar) \
    asm volatile("cp.async.bulk.shared::cluster.global.mbarrier::complete_tx::bytes " \
                 "[%0], [%1], %2, [%3];" \
        :: "r"((uint32_t)(smem_addr)), "l"(gptr), "r"((uint32_t)(bytes)), "r"((uint32_t)(mbar)) : "memory")

__device__ __forceinline__ void lds64f(uint32_t a, float& f0, float& f1) {
    asm volatile("ld.shared.v2.f32 {%0,%1}, [%2];" : "=f"(f0), "=f"(f1) : "r"(a));
}
__device__ __forceinline__ void lds128(uint32_t a, uint32_t& r0, uint32_t& r1, uint32_t& r2, uint32_t& r3) {
    asm volatile("ld.shared.v4.b32 {%0,%1,%2,%3}, [%4];"
                 : "=r"(r0), "=r"(r1), "=r"(r2), "=r"(r3) : "r"(a));
}
// pack: {lo -> low 16 bits, hi -> high 16 bits}
__device__ __forceinline__ uint32_t f2h2(float hi, float lo) {
    uint32_t r;
    asm("cvt.rn.f16x2.f32 %0, %1, %2;" : "=r"(r) : "f"(hi), "f"(lo));
    return r;
}
__device__ __forceinline__ void mma_f16(float* d, uint32_t a0, uint32_t a1, uint32_t a2, uint32_t a3,
                                        uint32_t b0, uint32_t b1) {
    asm volatile(
        "mma.sync.aligned.m16n8k16.row.col.f32.f16.f16.f32 "
        "{%0,%1,%2,%3}, {%4,%5,%6,%7}, {%8,%9}, {%0,%1,%2,%3};"
        : "+f"(d[0]), "+f"(d[1]), "+f"(d[2]), "+f"(d[3])
        : "r"(a0), "r"(a1), "r"(a2), "r"(a3), "r"(b0), "r"(b1));
}

// ---------------- config ----------------
static constexpr int KQ          = 2048;          // K per CTA (quarter)
static constexpr int KC          = 32;            // K per chunk (2 k16-steps)
static constexpr int NK          = KQ / KC;       // 64 chunks
static constexpr int STAGES      = 4;
static constexpr int W_STAGE     = 32768;         // 32 cols x 256 rows x 4B (SW128)
static constexpr int X_STAGE     = 8192;          // fp16 x fragments per chunk
static constexpr int STAGE_BYTES = W_STAGE + X_STAGE;  // 40 KB
static constexpr int SMEM_HDR    = 1024;
static constexpr int SMEM_BYTES  = SMEM_HDR + STAGES * STAGE_BYTES;  // 164864
static constexpr int OFF_FULL    = 0;
static constexpr int OFF_EMPTY   = 64;
static constexpr int NCONS       = 16;            // consumer warps (4/SMSP)

__device__ uint4  g_xpack[131072];         // x as fp16 A-fragments (2MB)
__device__ float  g_P[3][128 * 8192];      // k-quarter partials 1..3 of x@W^T
__device__ float  g_Y2[4][128 * 512];      // k-quarter partials of x@A^T

__global__ void dummy_k() {}

// ---------------- prep: x -> fp16 A-fragment order (validated in r10) ----------------
// group g in chunk kc: lg=g&31, mb=(g>>5)&7, s=g>>8
//   m = mb*16 + lg/4, c = s*16 + (lg&3)*2
__global__ void __launch_bounds__(256)
prep_x(const float* __restrict__ x)
{
    __shared__ float sm[128][33];
    const int kc   = blockIdx.x;        // 0..255
    const int tid  = threadIdx.x;
    const int w    = tid >> 5;
    const int lane = tid & 31;
    const int k0   = kc * 32;

    #pragma unroll
    for (int i = 0; i < 16; i++) {
        int m = w * 16 + i;
        sm[m][lane] = x[(size_t)m * 8192 + k0 + lane];
    }
    __syncthreads();

    uint4* dst = g_xpack + (size_t)kc * 512;
    #pragma unroll
    for (int pass = 0; pass < 2; pass++) {
        int g  = tid + pass * 256;
        int lg = g & 31, mb = (g >> 5) & 7, s = g >> 8;
        int m = mb * 16 + (lg >> 2);
        int c = s * 16 + (lg & 3) * 2;
        uint4 v;
        v.x = f2h2(sm[m][c + 1],     sm[m][c]);
        v.y = f2h2(sm[m + 8][c + 1], sm[m + 8][c]);
        v.z = f2h2(sm[m][c + 9],     sm[m][c + 8]);
        v.w = f2h2(sm[m + 8][c + 9], sm[m + 8][c + 8]);
        dst[g] = v;
    }
}

// ---------------- GEMM kernel ----------------
// bid<128: W tile (bid>>2)*256 rows, kq=bid&3.  bid>=128: A tile, same split.
// 16 consumer warps: wm = wid&1 (64 x-rows), nw = (wid>>1)*32. 1 producer warp.
__global__ void __launch_bounds__(544, 1)
lokr_gemm(const __grid_constant__ CUtensorMap w_map,
          const __grid_constant__ CUtensorMap a_map,
          float* __restrict__ d_out)
{
    extern __shared__ char smem[];
    const uint32_t sb = smem_u32(smem);
    const int tid  = threadIdx.x;
    const int wid  = tid >> 5;
    const int lane = tid & 31;

    const bool isA = (blockIdx.x >= 128);
    const int  b   = isA ? (blockIdx.x - 128) : blockIdx.x;
    const int  kq  = b & 3;
    const int  row0 = (b >> 2) * 256;
    const CUtensorMap* wm_map = isA ? &a_map : &w_map;

    if (tid == 0) {
        #pragma unroll
        for (int s = 0; s < STAGES; s++) {
            MBARRIER_INIT(sb + OFF_FULL  + s * 8, 1);
            MBARRIER_INIT(sb + OFF_EMPTY + s * 8, NCONS);
        }
    }
    __syncthreads();

    if (tid == NCONS * 32) {
        // ---------------- producer ----------------
        const char* xsrc = reinterpret_cast<const char*>(g_xpack) + (size_t)kq * (64 * X_STAGE);
        int es = 0, eph = 1;
        for (int c = 0; c < NK; c++) {
            MBARRIER_WAIT_PARITY(sb + OFF_EMPTY + es * 8, eph);
            uint32_t full = sb + OFF_FULL + es * 8;
            MBARRIER_EXPECT_TX(full, STAGE_BYTES);
            uint32_t st = sb + SMEM_HDR + es * STAGE_BYTES;
            TMA_LOAD_2D(st, wm_map, kq * KQ + c * KC, row0, full);
            BULK_LOAD(st + W_STAGE, xsrc + (size_t)c * X_STAGE, X_STAGE, full);
            if (++es == STAGES) { es = 0; eph ^= 1; }
        }
    } else if (wid < NCONS) {
        // ---------------- consumers ----------------
        float acc[4][4][4] = {};             // [i: x m16-block][j: W n8-block][frag]
        const int wm = wid & 1;              // x-row half (64 rows)
        const int nw = (wid >> 1) * 32;      // W-row slice (32 rows)
        const int r8 = lane >> 2;
        const int q  = lane & 3;
        // W pair addresses in SW128 fp32: row n, col c=s*16+q*2 (+8)
        //   addr = n*128 + ((u ^ (n&7))<<4) + (q&1)*8,  u = s*4 + (q>>1) (+2 for +8)
        uint32_t o0[2], o1[2];
        #pragma unroll
        for (int s = 0; s < 2; s++) {
            uint32_t u = (uint32_t)(s * 4 + (q >> 1));
            o0[s] = (((u    ) ^ (uint32_t)r8) << 4) + (uint32_t)((q & 1) * 8);
            o1[s] = (((u + 2) ^ (uint32_t)r8) << 4) + (uint32_t)((q & 1) * 8);
        }
        const uint32_t pbW = (uint32_t)((nw + r8) * 128);
        const uint32_t xfb = (uint32_t)W_STAGE + (uint32_t)lane * 16;

        int cs = 0, cph = 0;
        for (int c = 0; c < NK; c++) {
            MBARRIER_WAIT_PARITY(sb + OFF_FULL + cs * 8, cph);
            const uint32_t stg = sb + SMEM_HDR + (uint32_t)cs * STAGE_BYTES;
            const uint32_t wb  = stg + pbW;

            #pragma unroll
            for (int s = 0; s < 2; s++) {
                // W fragments: 8 LDS.64 fp32 + 8 cvt -> 4 n8-blocks x (b0,b1)
                uint32_t ub[4][2];
                #pragma unroll
                for (int j = 0; j < 4; j++) {
                    float f0, f1, g0, g1;
                    lds64f(wb + (uint32_t)(j * 1024) + o0[s], f0, f1);
                    lds64f(wb + (uint32_t)(j * 1024) + o1[s], g0, g1);
                    ub[j][0] = f2h2(f1, f0);
                    ub[j][1] = f2h2(g1, g0);
                }
                // x fragments: one LDS.128 per m16-block (fp16, prepacked)
                #pragma unroll
                for (int i = 0; i < 4; i++) {
                    uint32_t a0, a1, a2, a3;
                    lds128(stg + xfb + (uint32_t)((s * 8 + wm * 4 + i) << 9), a0, a1, a2, a3);
                    #pragma unroll
                    for (int j = 0; j < 4; j++)
                        mma_f16(acc[i][j], a0, a1, a2, a3, ub[j][0], ub[j][1]);
                }
            }

            __syncwarp();
            if (lane == 0) MBARRIER_ARRIVE(sb + OFF_EMPTY + cs * 8);
            if (++cs == STAGES) { cs = 0; cph ^= 1; }
        }

        // ---------------- epilogue ----------------
        float* ob;
        int stride;
        if (isA) { ob = g_Y2[kq]; stride = 512; }
        else     { ob = kq ? g_P[kq - 1] : d_out; stride = 8192; }
        #pragma unroll
        for (int i = 0; i < 4; i++) {
            #pragma unroll
            for (int j = 0; j < 4; j++) {
                int m = wm * 64 + 16 * i + r8;
                int n = row0 + nw + 8 * j + 2 * q;
                *reinterpret_cast<float2*>(&ob[(size_t)m * stride + n]) =
                    make_float2(acc[i][j][0], acc[i][j][1]);
                *reinterpret_cast<float2*>(&ob[(size_t)(m + 8) * stride + n]) =
                    make_float2(acc[i][j][2], acc[i][j][3]);
            }
        }
    }
}

// ---------------- combine kernel ----------------
__global__ void __launch_bounds__(256)
lokr_combine(const float* __restrict__ lokrB, const float* __restrict__ scalar,
             float* __restrict__ out)
{
    int idx = blockIdx.x * blockDim.x + threadIdx.x;   // float4 id, 0..262143
    int m = idx >> 11;
    int r = idx & 2047;
    int yi = m * 512 + (r >> 2);
    float coef = 2.0f * scalar[0] *
        (g_Y2[0][yi] + g_Y2[1][yi] + g_Y2[2][yi] + g_Y2[3][yi]);

    float4 bv = reinterpret_cast<const float4*>(lokrB)[r & 3];
    float4 o  = reinterpret_cast<float4*>(out)[idx];
    float4 a  = reinterpret_cast<const float4*>(g_P[0])[idx];
    float4 b  = reinterpret_cast<const float4*>(g_P[1])[idx];
    float4 c  = reinterpret_cast<const float4*>(g_P[2])[idx];
    o.x += a.x + b.x + c.x + coef * bv.x;
    o.y += a.y + b.y + c.y + coef * bv.y;
    o.z += a.z + b.z + c.z + coef * bv.z;
    o.w += a.w + b.w + c.w + coef * bv.w;
    reinterpret_cast<float4*>(out)[idx] = o;
}

// ---------------- host ----------------
typedef CUresult (*EncodeFn)(CUtensorMap*, CUtensorMapDataType, cuuint32_t, void*,
                             const cuuint64_t*, const cuuint64_t*, const cuuint32_t*,
                             const cuuint32_t*, CUtensorMapInterleave, CUtensorMapSwizzle,
                             CUtensorMapL2promotion, CUtensorMapFloatOOBfill);

static void make_map2d(EncodeFn enc, CUtensorMap* m, const float* base, uint64_t rows) {
    cuuint64_t dims[2]    = { 8192ull, rows };
    cuuint64_t strides[1] = { 8192ull * sizeof(float) };
    cuuint32_t box[2]     = { 32u, 256u };
    cuuint32_t es[2]      = { 1u, 1u };
    enc(m, CU_TENSOR_MAP_DATA_TYPE_FLOAT32, 2, (void*)base,
        dims, strides, box, es,
        CU_TENSOR_MAP_INTERLEAVE_NONE, CU_TENSOR_MAP_SWIZZLE_128B,
        CU_TENSOR_MAP_L2_PROMOTION_L2_128B, CU_TENSOR_MAP_FLOAT_OOB_FILL_NONE);
}

extern "C" void kernel_launch(void* const* d_in, const int* in_sizes, int n_in,
                              void* d_out, int out_size)
{
    (void)in_sizes; (void)n_in; (void)out_size;
    const float* x  = (const float*)d_in[0];
    const float* W  = (const float*)d_in[1];
    const float* A  = (const float*)d_in[2];
    const float* B  = (const float*)d_in[3];
    const float* sc = (const float*)d_in[4];

    void* fn = nullptr;
    cudaDriverEntryPointQueryResult qr;
    cudaGetDriverEntryPointByVersion("cuTensorMapEncodeTiled", &fn, 12000,
                                     cudaEnableDefault, &qr);
    EncodeFn enc = (EncodeFn)fn;

    CUtensorMap wm, am;
    make_map2d(enc, &wm, W, 8192);
    make_map2d(enc, &am, A, 512);

    cudaFuncSetAttribute(lokr_gemm, cudaFuncAttributeMaxDynamicSharedMemorySize, SMEM_BYTES);

    // Keep ncu (-s 5 -c 1) landing on the GEMM.
    dummy_k<<<1, 1>>>();
    dummy_k<<<1, 1>>>();
    prep_x<<<256, 256>>>(x);
    lokr_gemm<<<136, 544, SMEM_BYTES>>>(wm, am, (float*)d_out);
    lokr_combine<<<1024, 256>>>(B, sc, (float*)d_out);
}

// round 13
// speedup vs baseline: 2.0705x; 1.0436x over previous
#include <cuda_runtime.h>
#include <cuda.h>
#include <cstdint>

// ============================================================
// out = x @ (W + s * kron(A,B) * 2)^T
// out[m,i] = (x@W^T)[m,i] + 2*s*B[i%16]*(x@A^T)[m, i/16]
//
// Round 13: round 12 with the mbarrier fix.
//   cp.async.mbarrier.arrive (non-noinc) self-balances the phase count
//   (increments pending at issue, arrives at completion) -> r12 hang.
//   .noinc consumes the init count: 64 producer lanes + 1 expect_tx = 65.
//   Everything else identical: pad-striped conflict-free W smem (160B
//   rows), LDGSTS W feed, prepacked fp16 x, fp16 m16n8k16 MMA,
//   16 consumers (4/SMSP) + 2 producers, 136 CTAs, 4 stages.
// ============================================================

__device__ __forceinline__ uint32_t smem_u32(const void* p) {
    uint32_t a;
    asm("{ .reg .u64 t; cvta.to.shared.u64 t, %1; cvt.u32.u64 %0, t; }" : "=r"(a) : "l"(p));
    return a;
}

#define MBARRIER_INIT(addr, cnt) \
    asm volatile("mbarrier.init.shared.b64 [%0], %1;" :: "r"((uint32_t)(addr)), "r"((uint32_t)(cnt)) : "memory")

#define MBARRIER_EXPECT_TX(addr, bytes) \
    asm volatile("mbarrier.arrive.expect_tx.shared.b64 _, [%0], %1;" :: "r"((uint32_t)(addr)), "r"((uint32_t)(bytes)) : "memory")

#define MBARRIER_ARRIVE(addr) \
    asm volatile("mbarrier.arrive.shared.b64 _, [%0];" :: "r"((uint32_t)(addr)) : "memory")

#define MBARRIER_WAIT_PARITY(mbar, parity) do {                                      \
    uint32_t _m = (uint32_t)(mbar); uint32_t _p = (uint32_t)(parity);                \
    asm volatile(                                                                    \
        "{\n\t.reg .pred P1;\n\t"                                                    \
        "WAIT_LOOP_%=:\n\t"                                                          \
        "mbarrier.try_wait.parity.shared.b64 P1, [%0], %1;\n\t"                      \
        "@P1 bra.uni WAIT_DONE_%=;\n\t"                                              \
        "bra.uni WAIT_LOOP_%=;\n\t"                                                  \
        "WAIT_DONE_%=:\n\t}"                                                         \
        :: "r"(_m), "r"(_p) : "memory");                                             \
} while (0)

#define BULK_LOAD(smem_addr, gptr, bytes, mbar) \
    asm volatile("cp.async.bulk.shared::cluster.global.mbarrier::complete_tx::bytes " \
                 "[%0], [%1], %2, [%3];" \
        :: "r"((uint32_t)(smem_addr)), "l"(gptr), "r"((uint32_t)(bytes)), "r"((uint32_t)(mbar)) : "memory")

#define CP_ASYNC16(smem, gptr) \
    asm volatile("cp.async.cg.shared.global [%0], [%1], 16;" \
        :: "r"((uint32_t)(smem)), "l"(gptr) : "memory")

// .noinc: arrive consumes the pre-initialized count when this thread's
// prior cp.asyncs complete (non-noinc form is self-balancing -> hang).
#define CP_ASYNC_MBAR_NOINC(mbar) \
    asm volatile("cp.async.mbarrier.arrive.noinc.shared::cta.b64 [%0];" \
        :: "r"((uint32_t)(mbar)) : "memory")

__device__ __forceinline__ void lds64f(uint32_t a, float& f0, float& f1) {
    asm volatile("ld.shared.v2.f32 {%0,%1}, [%2];" : "=f"(f0), "=f"(f1) : "r"(a));
}
__device__ __forceinline__ void lds128(uint32_t a, uint32_t& r0, uint32_t& r1, uint32_t& r2, uint32_t& r3) {
    asm volatile("ld.shared.v4.b32 {%0,%1,%2,%3}, [%4];"
                 : "=r"(r0), "=r"(r1), "=r"(r2), "=r"(r3) : "r"(a));
}
// pack: {lo -> low 16 bits, hi -> high 16 bits}
__device__ __forceinline__ uint32_t f2h2(float hi, float lo) {
    uint32_t r;
    asm("cvt.rn.f16x2.f32 %0, %1, %2;" : "=r"(r) : "f"(hi), "f"(lo));
    return r;
}
__device__ __forceinline__ void mma_f16(float* d, uint32_t a0, uint32_t a1, uint32_t a2, uint32_t a3,
                                        uint32_t b0, uint32_t b1) {
    asm volatile(
        "mma.sync.aligned.m16n8k16.row.col.f32.f16.f16.f32 "
        "{%0,%1,%2,%3}, {%4,%5,%6,%7}, {%8,%9}, {%0,%1,%2,%3};"
        : "+f"(d[0]), "+f"(d[1]), "+f"(d[2]), "+f"(d[3])
        : "r"(a0), "r"(a1), "r"(a2), "r"(a3), "r"(b0), "r"(b1));
}

// ---------------- config ----------------
static constexpr int KQ          = 2048;          // K per CTA (quarter)
static constexpr int KC          = 32;            // K per chunk (2 k16-steps)
static constexpr int NK          = KQ / KC;       // 64 chunks
static constexpr int STAGES      = 4;
static constexpr int W_ROW_B     = 160;           // 128B data + 32B pad (bank-stripe)
static constexpr int W_STAGE     = 256 * W_ROW_B; // 40960
static constexpr int X_STAGE     = 8192;          // fp16 x fragments per chunk
static constexpr int STAGE_BYTES = W_STAGE + X_STAGE;  // 49152
static constexpr int SMEM_HDR    = 1024;
static constexpr int SMEM_BYTES  = SMEM_HDR + STAGES * STAGE_BYTES;  // 197632
static constexpr int OFF_FULL    = 0;
static constexpr int OFF_EMPTY   = 64;
static constexpr int NCONS       = 16;            // consumer warps (4/SMSP)
static constexpr int NPROD       = 2;             // producer warps (LDGSTS)

__device__ uint4  g_xpack[131072];         // x as fp16 A-fragments (2MB)
__device__ float  g_P[3][128 * 8192];      // k-quarter partials 1..3 of x@W^T
__device__ float  g_Y2[4][128 * 512];      // k-quarter partials of x@A^T

__global__ void dummy_k() {}

// ---------------- prep: x -> fp16 A-fragment order (validated) ----------------
__global__ void __launch_bounds__(256)
prep_x(const float* __restrict__ x)
{
    __shared__ float sm[128][33];
    const int kc   = blockIdx.x;        // 0..255
    const int tid  = threadIdx.x;
    const int w    = tid >> 5;
    const int lane = tid & 31;
    const int k0   = kc * 32;

    #pragma unroll
    for (int i = 0; i < 16; i++) {
        int m = w * 16 + i;
        sm[m][lane] = x[(size_t)m * 8192 + k0 + lane];
    }
    __syncthreads();

    uint4* dst = g_xpack + (size_t)kc * 512;
    #pragma unroll
    for (int pass = 0; pass < 2; pass++) {
        int g  = tid + pass * 256;
        int lg = g & 31, mb = (g >> 5) & 7, s = g >> 8;
        int m = mb * 16 + (lg >> 2);
        int c = s * 16 + (lg & 3) * 2;
        uint4 v;
        v.x = f2h2(sm[m][c + 1],     sm[m][c]);
        v.y = f2h2(sm[m + 8][c + 1], sm[m + 8][c]);
        v.z = f2h2(sm[m][c + 9],     sm[m][c + 8]);
        v.w = f2h2(sm[m + 8][c + 9], sm[m + 8][c + 8]);
        dst[g] = v;
    }
}

// ---------------- GEMM kernel ----------------
// bid<128: W tile (bid>>2)*256 rows, kq=bid&3.  bid>=128: A tile, same split.
// warps 0..15 consumers (wm=wid&1: 64 x-rows; nw=(wid>>1)*32),
// warps 16..17 producers: 64 lanes LDGSTS W into pad-striped smem.
__global__ void __launch_bounds__(576, 1)
lokr_gemm(const float* __restrict__ Wp, const float* __restrict__ Ap,
          float* __restrict__ d_out)
{
    extern __shared__ char smem[];
    const uint32_t sb = smem_u32(smem);
    const int tid  = threadIdx.x;
    const int wid  = tid >> 5;
    const int lane = tid & 31;

    const bool isA = (blockIdx.x >= 128);
    const int  b   = isA ? (blockIdx.x - 128) : blockIdx.x;
    const int  kq  = b & 3;
    const int  row0 = (b >> 2) * 256;

    if (tid == 0) {
        #pragma unroll
        for (int s = 0; s < STAGES; s++) {
            // full: 64 producer-lane noinc arrives + 1 expect_tx arrive (x bulk)
            MBARRIER_INIT(sb + OFF_FULL  + s * 8, NPROD * 32 + 1);
            MBARRIER_INIT(sb + OFF_EMPTY + s * 8, NCONS);
        }
    }
    __syncthreads();

    if (wid >= NCONS) {
        // ---------------- producers (LDGSTS) ----------------
        const int pl = (wid - NCONS) * 32 + lane;   // 0..63
        const float* src   = isA ? Ap : Wp;
        const float* gbase = src + (size_t)row0 * 8192 + kq * KQ;
        const char*  xsrc  = reinterpret_cast<const char*>(g_xpack) + (size_t)kq * (64 * X_STAGE);

        int es = 0, eph = 1;
        for (int c = 0; c < NK; c++) {
            MBARRIER_WAIT_PARITY(sb + OFF_EMPTY + es * 8, eph);
            uint32_t full = sb + OFF_FULL + es * 8;
            uint32_t st   = sb + SMEM_HDR + es * STAGE_BYTES;
            if (pl == 0) {
                MBARRIER_EXPECT_TX(full, X_STAGE);
                BULK_LOAD(st + W_STAGE, xsrc + (size_t)c * X_STAGE, X_STAGE, full);
            }
            const float* g0 = gbase + c * KC;
            #pragma unroll
            for (int i = 0; i < 32; i++) {
                int g   = i * 64 + pl;        // 0..2047
                int row = g >> 3;             // 0..255
                int cb  = g & 7;              // 16B unit within row
                CP_ASYNC16(st + (uint32_t)(row * W_ROW_B + cb * 16),
                           g0 + (size_t)row * 8192 + cb * 4);
            }
            CP_ASYNC_MBAR_NOINC(full);        // arrives when this lane's copies land
            if (++es == STAGES) { es = 0; eph ^= 1; }
        }
    } else {
        // ---------------- consumers ----------------
        float acc[4][4][4] = {};             // [i: x m16-block][j: W n8-block][frag]
        const int wm = wid & 1;              // x-row half (64 rows)
        const int nw = (wid >> 1) * 32;      // W-row slice (32 rows)
        const int r8 = lane >> 2;
        const int q  = lane & 3;
        const uint32_t q8  = (uint32_t)(q * 8);
        const uint32_t pbW = (uint32_t)((nw + r8) * W_ROW_B);
        const uint32_t xfb = (uint32_t)W_STAGE + (uint32_t)lane * 16;

        int cs = 0, cph = 0;
        for (int c = 0; c < NK; c++) {
            MBARRIER_WAIT_PARITY(sb + OFF_FULL + cs * 8, cph);
            const uint32_t stg = sb + SMEM_HDR + (uint32_t)cs * STAGE_BYTES;
            const uint32_t wb  = stg + pbW + q8;

            #pragma unroll
            for (int s = 0; s < 2; s++) {
                const uint32_t so = (uint32_t)(s * 64);
                // W fragments: 8 LDS.64 fp32 (conflict-free, pad-striped) + cvt
                uint32_t ub[4][2];
                #pragma unroll
                for (int j = 0; j < 4; j++) {
                    float f0, f1, g0, g1;
                    lds64f(wb + (uint32_t)(j * 8 * W_ROW_B) + so,       f0, f1);
                    lds64f(wb + (uint32_t)(j * 8 * W_ROW_B) + so + 32u, g0, g1);
                    ub[j][0] = f2h2(f1, f0);
                    ub[j][1] = f2h2(g1, g0);
                }
                // x fragments: one LDS.128 per m16-block (fp16, prepacked)
                #pragma unroll
                for (int i = 0; i < 4; i++) {
                    uint32_t a0, a1, a2, a3;
                    lds128(stg + xfb + (uint32_t)((s * 8 + wm * 4 + i) << 9), a0, a1, a2, a3);
                    #pragma unroll
                    for (int j = 0; j < 4; j++)
                        mma_f16(acc[i][j], a0, a1, a2, a3, ub[j][0], ub[j][1]);
                }
            }

            __syncwarp();
            if (lane == 0) MBARRIER_ARRIVE(sb + OFF_EMPTY + cs * 8);
            if (++cs == STAGES) { cs = 0; cph ^= 1; }
        }

        // ---------------- epilogue ----------------
        float* ob;
        int stride;
        if (isA) { ob = g_Y2[kq]; stride = 512; }
        else     { ob = kq ? g_P[kq - 1] : d_out; stride = 8192; }
        #pragma unroll
        for (int i = 0; i < 4; i++) {
            #pragma unroll
            for (int j = 0; j < 4; j++) {
                int m = wm * 64 + 16 * i + r8;
                int n = row0 + nw + 8 * j + 2 * q;
                *reinterpret_cast<float2*>(&ob[(size_t)m * stride + n]) =
                    make_float2(acc[i][j][0], acc[i][j][1]);
                *reinterpret_cast<float2*>(&ob[(size_t)(m + 8) * stride + n]) =
                    make_float2(acc[i][j][2], acc[i][j][3]);
            }
        }
    }
}

// ---------------- combine kernel ----------------
__global__ void __launch_bounds__(256)
lokr_combine(const float* __restrict__ lokrB, const float* __restrict__ scalar,
             float* __restrict__ out)
{
    int idx = blockIdx.x * blockDim.x + threadIdx.x;   // float4 id, 0..262143
    int m = idx >> 11;
    int r = idx & 2047;
    int yi = m * 512 + (r >> 2);
    float coef = 2.0f * scalar[0] *
        (g_Y2[0][yi] + g_Y2[1][yi] + g_Y2[2][yi] + g_Y2[3][yi]);

    float4 bv = reinterpret_cast<const float4*>(lokrB)[r & 3];
    float4 o  = reinterpret_cast<float4*>(out)[idx];
    float4 a  = reinterpret_cast<const float4*>(g_P[0])[idx];
    float4 b  = reinterpret_cast<const float4*>(g_P[1])[idx];
    float4 c  = reinterpret_cast<const float4*>(g_P[2])[idx];
    o.x += a.x + b.x + c.x + coef * bv.x;
    o.y += a.y + b.y + c.y + coef * bv.y;
    o.z += a.z + b.z + c.z + coef * bv.z;
    o.w += a.w + b.w + c.w + coef * bv.w;
    reinterpret_cast<float4*>(out)[idx] = o;
}

// ---------------- host ----------------
extern "C" void kernel_launch(void* const* d_in, const int* in_sizes, int n_in,
                              void* d_out, int out_size)
{
    (void)in_sizes; (void)n_in; (void)out_size;
    const float* x  = (const float*)d_in[0];
    const float* W  = (const float*)d_in[1];
    const float* A  = (const float*)d_in[2];
    const float* B  = (const float*)d_in[3];
    const float* sc = (const float*)d_in[4];

    cudaFuncSetAttribute(lokr_gemm, cudaFuncAttributeMaxDynamicSharedMemorySize, SMEM_BYTES);

    // Keep ncu (-s 5 -c 1) landing on the GEMM.
    dummy_k<<<1, 1>>>();
    dummy_k<<<1, 1>>>();
    prep_x<<<256, 256>>>(x);
    lokr_gemm<<<136, 576, SMEM_BYTES>>>(W, A, (float*)d_out);
    lokr_combine<<<1024, 256>>>(B, sc, (float*)d_out);
}

// round 14
// speedup vs baseline: 2.2523x; 1.0878x over previous
#include <cuda_runtime.h>
#include <cuda.h>
#include <cstdint>

// ============================================================
// out = x @ (W + s * kron(A,B) * 2)^T
// out[m,i] = (x@W^T)[m,i] + 2*s*B[i%16]*(x@A^T)[m, i/16]
//
// Round 14: de-convoy. M_CTA 256->128, 272 CTAs, 2 CTAs/SM
//   (two independent barrier domains per SM; same per-SM totals).
//   8 consumers + 1 producer per CTA; pad-striped conflict-free W smem,
//   LDGSTS W feed (.noinc mbarrier), prepacked fp16 x, fp16 m16n8k16.
// ============================================================

__device__ __forceinline__ uint32_t smem_u32(const void* p) {
    uint32_t a;
    asm("{ .reg .u64 t; cvta.to.shared.u64 t, %1; cvt.u32.u64 %0, t; }" : "=r"(a) : "l"(p));
    return a;
}

#define MBARRIER_INIT(addr, cnt) \
    asm volatile("mbarrier.init.shared.b64 [%0], %1;" :: "r"((uint32_t)(addr)), "r"((uint32_t)(cnt)) : "memory")

#define MBARRIER_EXPECT_TX(addr, bytes) \
    asm volatile("mbarrier.arrive.expect_tx.shared.b64 _, [%0], %1;" :: "r"((uint32_t)(addr)), "r"((uint32_t)(bytes)) : "memory")

#define MBARRIER_ARRIVE(addr) \
    asm volatile("mbarrier.arrive.shared.b64 _, [%0];" :: "r"((uint32_t)(addr)) : "memory")

#define MBARRIER_WAIT_PARITY(mbar, parity) do {                                      \
    uint32_t _m = (uint32_t)(mbar); uint32_t _p = (uint32_t)(parity);                \
    asm volatile(                                                                    \
        "{\n\t.reg .pred P1;\n\t"                                                    \
        "WAIT_LOOP_%=:\n\t"                                                          \
        "mbarrier.try_wait.parity.shared.b64 P1, [%0], %1;\n\t"                      \
        "@P1 bra.uni WAIT_DONE_%=;\n\t"                                              \
        "bra.uni WAIT_LOOP_%=;\n\t"                                                  \
        "WAIT_DONE_%=:\n\t}"                                                         \
        :: "r"(_m), "r"(_p) : "memory");                                             \
} while (0)

#define BULK_LOAD(smem_addr, gptr, bytes, mbar) \
    asm volatile("cp.async.bulk.shared::cluster.global.mbarrier::complete_tx::bytes " \
                 "[%0], [%1], %2, [%3];" \
        :: "r"((uint32_t)(smem_addr)), "l"(gptr), "r"((uint32_t)(bytes)), "r"((uint32_t)(mbar)) : "memory")

#define CP_ASYNC16(smem, gptr) \
    asm volatile("cp.async.cg.shared.global [%0], [%1], 16;" \
        :: "r"((uint32_t)(smem)), "l"(gptr) : "memory")

#define CP_ASYNC_MBAR_NOINC(mbar) \
    asm volatile("cp.async.mbarrier.arrive.noinc.shared::cta.b64 [%0];" \
        :: "r"((uint32_t)(mbar)) : "memory")

__device__ __forceinline__ void lds64f(uint32_t a, float& f0, float& f1) {
    asm volatile("ld.shared.v2.f32 {%0,%1}, [%2];" : "=f"(f0), "=f"(f1) : "r"(a));
}
__device__ __forceinline__ void lds128(uint32_t a, uint32_t& r0, uint32_t& r1, uint32_t& r2, uint32_t& r3) {
    asm volatile("ld.shared.v4.b32 {%0,%1,%2,%3}, [%4];"
                 : "=r"(r0), "=r"(r1), "=r"(r2), "=r"(r3) : "r"(a));
}
__device__ __forceinline__ uint32_t f2h2(float hi, float lo) {
    uint32_t r;
    asm("cvt.rn.f16x2.f32 %0, %1, %2;" : "=r"(r) : "f"(hi), "f"(lo));
    return r;
}
__device__ __forceinline__ void mma_f16(float* d, uint32_t a0, uint32_t a1, uint32_t a2, uint32_t a3,
                                        uint32_t b0, uint32_t b1) {
    asm volatile(
        "mma.sync.aligned.m16n8k16.row.col.f32.f16.f16.f32 "
        "{%0,%1,%2,%3}, {%4,%5,%6,%7}, {%8,%9}, {%0,%1,%2,%3};"
        : "+f"(d[0]), "+f"(d[1]), "+f"(d[2]), "+f"(d[3])
        : "r"(a0), "r"(a1), "r"(a2), "r"(a3), "r"(b0), "r"(b1));
}

// ---------------- config ----------------
static constexpr int KQ          = 2048;          // K per CTA (quarter)
static constexpr int KC          = 32;            // K per chunk (2 k16-steps)
static constexpr int NK          = KQ / KC;       // 64 chunks
static constexpr int STAGES      = 3;
static constexpr int W_ROWS      = 128;           // W rows per CTA
static constexpr int W_ROW_B     = 160;           // 128B data + 32B pad (bank-stripe)
static constexpr int W_STAGE     = W_ROWS * W_ROW_B;   // 20480
static constexpr int X_STAGE     = 8192;          // fp16 x fragments per chunk
static constexpr int STAGE_BYTES = W_STAGE + X_STAGE;  // 28672
static constexpr int SMEM_HDR    = 1024;
static constexpr int SMEM_BYTES  = SMEM_HDR + STAGES * STAGE_BYTES;  // 87040 (x2 CTAs/SM)
static constexpr int OFF_FULL    = 0;
static constexpr int OFF_EMPTY   = 64;
static constexpr int NCONS       = 8;             // consumer warps per CTA

__device__ uint4  g_xpack[131072];         // x as fp16 A-fragments (2MB)
__device__ float  g_P[3][128 * 8192];      // k-quarter partials 1..3 of x@W^T
__device__ float  g_Y2[4][128 * 512];      // k-quarter partials of x@A^T

__global__ void dummy_k() {}

// ---------------- prep: x -> fp16 A-fragment order (validated) ----------------
__global__ void __launch_bounds__(256)
prep_x(const float* __restrict__ x)
{
    __shared__ float sm[128][33];
    const int kc   = blockIdx.x;        // 0..255
    const int tid  = threadIdx.x;
    const int w    = tid >> 5;
    const int lane = tid & 31;
    const int k0   = kc * 32;

    #pragma unroll
    for (int i = 0; i < 16; i++) {
        int m = w * 16 + i;
        sm[m][lane] = x[(size_t)m * 8192 + k0 + lane];
    }
    __syncthreads();

    uint4* dst = g_xpack + (size_t)kc * 512;
    #pragma unroll
    for (int pass = 0; pass < 2; pass++) {
        int g  = tid + pass * 256;
        int lg = g & 31, mb = (g >> 5) & 7, s = g >> 8;
        int m = mb * 16 + (lg >> 2);
        int c = s * 16 + (lg & 3) * 2;
        uint4 v;
        v.x = f2h2(sm[m][c + 1],     sm[m][c]);
        v.y = f2h2(sm[m + 8][c + 1], sm[m + 8][c]);
        v.z = f2h2(sm[m][c + 9],     sm[m][c + 8]);
        v.w = f2h2(sm[m + 8][c + 9], sm[m + 8][c + 8]);
        dst[g] = v;
    }
}

// ---------------- GEMM kernel ----------------
// bid<256: W tile (bid>>2)*128 rows, kq=bid&3.  bid>=256: A tile ((bid-256)>>2)*128, kq.
// warps 0..7 consumers (wm=wid&1: 64 x-rows; nw=(wid>>1)*32: 32 W-rows),
// warp 8 producer: 32 lanes LDGSTS W into pad-striped smem + x bulk.
__global__ void __launch_bounds__(288, 2)
lokr_gemm(const float* __restrict__ Wp, const float* __restrict__ Ap,
          float* __restrict__ d_out)
{
    extern __shared__ char smem[];
    const uint32_t sb = smem_u32(smem);
    const int tid  = threadIdx.x;
    const int wid  = tid >> 5;
    const int lane = tid & 31;

    const bool isA = (blockIdx.x >= 256);
    const int  b   = isA ? (blockIdx.x - 256) : blockIdx.x;
    const int  kq  = b & 3;
    const int  row0 = (b >> 2) * W_ROWS;

    if (tid == 0) {
        #pragma unroll
        for (int s = 0; s < STAGES; s++) {
            // full: 32 producer-lane noinc arrives + 1 expect_tx arrive (x bulk)
            MBARRIER_INIT(sb + OFF_FULL  + s * 8, 33);
            MBARRIER_INIT(sb + OFF_EMPTY + s * 8, NCONS);
        }
    }
    __syncthreads();

    if (wid == NCONS) {
        // ---------------- producer (LDGSTS) ----------------
        const float* src   = isA ? Ap : Wp;
        const float* gbase = src + (size_t)row0 * 8192 + kq * KQ;
        const char*  xsrc  = reinterpret_cast<const char*>(g_xpack) + (size_t)kq * (64 * X_STAGE);

        int es = 0, eph = 1;
        for (int c = 0; c < NK; c++) {
            MBARRIER_WAIT_PARITY(sb + OFF_EMPTY + es * 8, eph);
            uint32_t full = sb + OFF_FULL + es * 8;
            uint32_t st   = sb + SMEM_HDR + es * STAGE_BYTES;
            if (lane == 0) {
                MBARRIER_EXPECT_TX(full, X_STAGE);
                BULK_LOAD(st + W_STAGE, xsrc + (size_t)c * X_STAGE, X_STAGE, full);
            }
            const float* g0 = gbase + c * KC;
            #pragma unroll
            for (int i = 0; i < 32; i++) {
                int g   = i * 32 + lane;      // 0..1023
                int row = g >> 3;             // 0..127
                int cb  = g & 7;              // 16B unit within row
                CP_ASYNC16(st + (uint32_t)(row * W_ROW_B + cb * 16),
                           g0 + (size_t)row * 8192 + cb * 4);
            }
            CP_ASYNC_MBAR_NOINC(full);        // arrives when this lane's copies land
            if (++es == STAGES) { es = 0; eph ^= 1; }
        }
    } else {
        // ---------------- consumers ----------------
        float acc[4][4][4] = {};             // [i: x m16-block][j: W n8-block][frag]
        const int wm = wid & 1;              // x-row half (64 rows)
        const int nw = (wid >> 1) * 32;      // W-row slice (32 rows of 128)
        const int r8 = lane >> 2;
        const int q  = lane & 3;
        const uint32_t q8  = (uint32_t)(q * 8);
        const uint32_t pbW = (uint32_t)((nw + r8) * W_ROW_B);
        const uint32_t xfb = (uint32_t)W_STAGE + (uint32_t)lane * 16;

        int cs = 0, cph = 0;
        for (int c = 0; c < NK; c++) {
            MBARRIER_WAIT_PARITY(sb + OFF_FULL + cs * 8, cph);
            const uint32_t stg = sb + SMEM_HDR + (uint32_t)cs * STAGE_BYTES;
            const uint32_t wb  = stg + pbW + q8;

            #pragma unroll
            for (int s = 0; s < 2; s++) {
                const uint32_t so = (uint32_t)(s * 64);
                // W fragments: 8 LDS.64 fp32 (conflict-free, pad-striped) + cvt
                uint32_t ub[4][2];
                #pragma unroll
                for (int j = 0; j < 4; j++) {
                    float f0, f1, g0, g1;
                    lds64f(wb + (uint32_t)(j * 8 * W_ROW_B) + so,       f0, f1);
                    lds64f(wb + (uint32_t)(j * 8 * W_ROW_B) + so + 32u, g0, g1);
                    ub[j][0] = f2h2(f1, f0);
                    ub[j][1] = f2h2(g1, g0);
                }
                // x fragments: one LDS.128 per m16-block (fp16, prepacked)
                #pragma unroll
                for (int i = 0; i < 4; i++) {
                    uint32_t a0, a1, a2, a3;
                    lds128(stg + xfb + (uint32_t)((s * 8 + wm * 4 + i) << 9), a0, a1, a2, a3);
                    #pragma unroll
                    for (int j = 0; j < 4; j++)
                        mma_f16(acc[i][j], a0, a1, a2, a3, ub[j][0], ub[j][1]);
                }
            }

            __syncwarp();
            if (lane == 0) MBARRIER_ARRIVE(sb + OFF_EMPTY + cs * 8);
            if (++cs == STAGES) { cs = 0; cph ^= 1; }
        }

        // ---------------- epilogue ----------------
        float* ob;
        int stride;
        if (isA) { ob = g_Y2[kq]; stride = 512; }
        else     { ob = kq ? g_P[kq - 1] : d_out; stride = 8192; }
        #pragma unroll
        for (int i = 0; i < 4; i++) {
            #pragma unroll
            for (int j = 0; j < 4; j++) {
                int m = wm * 64 + 16 * i + r8;
                int n = row0 + nw + 8 * j + 2 * q;
                *reinterpret_cast<float2*>(&ob[(size_t)m * stride + n]) =
                    make_float2(acc[i][j][0], acc[i][j][1]);
                *reinterpret_cast<float2*>(&ob[(size_t)(m + 8) * stride + n]) =
                    make_float2(acc[i][j][2], acc[i][j][3]);
            }
        }
    }
}

// ---------------- combine kernel ----------------
__global__ void __launch_bounds__(256)
lokr_combine(const float* __restrict__ lokrB, const float* __restrict__ scalar,
             float* __restrict__ out)
{
    int idx = blockIdx.x * blockDim.x + threadIdx.x;   // float4 id, 0..262143
    int m = idx >> 11;
    int r = idx & 2047;
    int yi = m * 512 + (r >> 2);
    float coef = 2.0f * scalar[0] *
        (g_Y2[0][yi] + g_Y2[1][yi] + g_Y2[2][yi] + g_Y2[3][yi]);

    float4 bv = reinterpret_cast<const float4*>(lokrB)[r & 3];
    float4 o  = reinterpret_cast<float4*>(out)[idx];
    float4 a  = reinterpret_cast<const float4*>(g_P[0])[idx];
    float4 b  = reinterpret_cast<const float4*>(g_P[1])[idx];
    float4 c  = reinterpret_cast<const float4*>(g_P[2])[idx];
    o.x += a.x + b.x + c.x + coef * bv.x;
    o.y += a.y + b.y + c.y + coef * bv.y;
    o.z += a.z + b.z + c.z + coef * bv.z;
    o.w += a.w + b.w + c.w + coef * bv.w;
    reinterpret_cast<float4*>(out)[idx] = o;
}

// ---------------- host ----------------
extern "C" void kernel_launch(void* const* d_in, const int* in_sizes, int n_in,
                              void* d_out, int out_size)
{
    (void)in_sizes; (void)n_in; (void)out_size;
    const float* x  = (const float*)d_in[0];
    const float* W  = (const float*)d_in[1];
    const float* A  = (const float*)d_in[2];
    const float* B  = (const float*)d_in[3];
    const float* sc = (const float*)d_in[4];

    cudaFuncSetAttribute(lokr_gemm, cudaFuncAttributeMaxDynamicSharedMemorySize, SMEM_BYTES);

    // Keep ncu (-s 5 -c 1) landing on the GEMM.
    dummy_k<<<1, 1>>>();
    dummy_k<<<1, 1>>>();
    prep_x<<<256, 256>>>(x);
    lokr_gemm<<<272, 288, SMEM_BYTES>>>(W, A, (float*)d_out);
    lokr_combine<<<1024, 256>>>(B, sc, (float*)d_out);
}

// round 16
// speedup vs baseline: 2.4513x; 1.0883x over previous
#include <cuda_runtime.h>
#include <cuda.h>
#include <cstdint>

// ============================================================
// out = x @ (W + s * kron(A,B) * 2)^T
// out[m,i] = (x@W^T)[m,i] + 2*s*B[i%16]*(x@A^T)[m, i/16]
//
// Round 16: r14 champion geometry (272 CTAs, M_CTA=128, 2 CTAs/SM)
//   with KC 32->64 (256B-contiguous W reads, half the barrier events),
//   STAGES 3->2, 2 producer warps (64 LDGSTS lanes), dummies removed.
//   Pad-striped conflict-free W smem (288B rows: same mod-32 bank
//   stripe as 160B), prepacked fp16 x, fp16 m16n8k16 MMA.
// ============================================================

__device__ __forceinline__ uint32_t smem_u32(const void* p) {
    uint32_t a;
    asm("{ .reg .u64 t; cvta.to.shared.u64 t, %1; cvt.u32.u64 %0, t; }" : "=r"(a) : "l"(p));
    return a;
}

#define MBARRIER_INIT(addr, cnt) \
    asm volatile("mbarrier.init.shared.b64 [%0], %1;" :: "r"((uint32_t)(addr)), "r"((uint32_t)(cnt)) : "memory")

#define MBARRIER_EXPECT_TX(addr, bytes) \
    asm volatile("mbarrier.arrive.expect_tx.shared.b64 _, [%0], %1;" :: "r"((uint32_t)(addr)), "r"((uint32_t)(bytes)) : "memory")

#define MBARRIER_ARRIVE(addr) \
    asm volatile("mbarrier.arrive.shared.b64 _, [%0];" :: "r"((uint32_t)(addr)) : "memory")

#define MBARRIER_WAIT_PARITY(mbar, parity) do {                                      \
    uint32_t _m = (uint32_t)(mbar); uint32_t _p = (uint32_t)(parity);                \
    asm volatile(                                                                    \
        "{\n\t.reg .pred P1;\n\t"                                                    \
        "WAIT_LOOP_%=:\n\t"                                                          \
        "mbarrier.try_wait.parity.shared.b64 P1, [%0], %1;\n\t"                      \
        "@P1 bra.uni WAIT_DONE_%=;\n\t"                                              \
        "bra.uni WAIT_LOOP_%=;\n\t"                                                  \
        "WAIT_DONE_%=:\n\t}"                                                         \
        :: "r"(_m), "r"(_p) : "memory");                                             \
} while (0)

#define BULK_LOAD(smem_addr, gptr, bytes, mbar) \
    asm volatile("cp.async.bulk.shared::cluster.global.mbarrier::complete_tx::bytes " \
                 "[%0], [%1], %2, [%3];" \
        :: "r"((uint32_t)(smem_addr)), "l"(gptr), "r"((uint32_t)(bytes)), "r"((uint32_t)(mbar)) : "memory")

#define CP_ASYNC16(smem, gptr) \
    asm volatile("cp.async.cg.shared.global [%0], [%1], 16;" \
        :: "r"((uint32_t)(smem)), "l"(gptr) : "memory")

#define CP_ASYNC_MBAR_NOINC(mbar) \
    asm volatile("cp.async.mbarrier.arrive.noinc.shared::cta.b64 [%0];" \
        :: "r"((uint32_t)(mbar)) : "memory")

__device__ __forceinline__ void lds64f(uint32_t a, float& f0, float& f1) {
    asm volatile("ld.shared.v2.f32 {%0,%1}, [%2];" : "=f"(f0), "=f"(f1) : "r"(a));
}
__device__ __forceinline__ void lds128(uint32_t a, uint32_t& r0, uint32_t& r1, uint32_t& r2, uint32_t& r3) {
    asm volatile("ld.shared.v4.b32 {%0,%1,%2,%3}, [%4];"
                 : "=r"(r0), "=r"(r1), "=r"(r2), "=r"(r3) : "r"(a));
}
__device__ __forceinline__ uint32_t f2h2(float hi, float lo) {
    uint32_t r;
    asm("cvt.rn.f16x2.f32 %0, %1, %2;" : "=r"(r) : "f"(hi), "f"(lo));
    return r;
}
__device__ __forceinline__ void mma_f16(float* d, uint32_t a0, uint32_t a1, uint32_t a2, uint32_t a3,
                                        uint32_t b0, uint32_t b1) {
    asm volatile(
        "mma.sync.aligned.m16n8k16.row.col.f32.f16.f16.f32 "
        "{%0,%1,%2,%3}, {%4,%5,%6,%7}, {%8,%9}, {%0,%1,%2,%3};"
        : "+f"(d[0]), "+f"(d[1]), "+f"(d[2]), "+f"(d[3])
        : "r"(a0), "r"(a1), "r"(a2), "r"(a3), "r"(b0), "r"(b1));
}

// ---------------- config ----------------
static constexpr int KQ          = 2048;          // K per CTA (quarter)
static constexpr int KC          = 64;            // K per chunk (4 k16-steps)
static constexpr int NK          = KQ / KC;       // 32 chunks
static constexpr int STAGES      = 2;
static constexpr int W_ROWS      = 128;           // W rows per CTA
static constexpr int W_ROW_B     = 288;           // 256B data + 32B pad (same bank stripe as 160)
static constexpr int W_STAGE     = W_ROWS * W_ROW_B;   // 36864
static constexpr int X_STAGE     = 16384;         // fp16 x fragments per 64-wide chunk
static constexpr int STAGE_BYTES = W_STAGE + X_STAGE;  // 53248
static constexpr int SMEM_HDR    = 1024;
static constexpr int SMEM_BYTES  = SMEM_HDR + STAGES * STAGE_BYTES;  // 107520 (2 CTAs/SM)
static constexpr int OFF_FULL    = 0;
static constexpr int OFF_EMPTY   = 64;
static constexpr int NCONS       = 8;             // consumer warps per CTA
static constexpr int NPROD       = 2;             // producer warps per CTA

__device__ uint4  g_xpack[131072];         // x as fp16 A-fragments (2MB)
__device__ float  g_P[3][128 * 8192];      // k-quarter partials 1..3 of x@W^T
__device__ float  g_Y2[4][128 * 512];      // k-quarter partials of x@A^T

// ---------------- prep: x -> fp16 A-fragment order (validated) ----------------
__global__ void __launch_bounds__(256)
prep_x(const float* __restrict__ x)
{
    __shared__ float sm[128][33];
    const int kc   = blockIdx.x;        // 0..255 (32-wide chunk)
    const int tid  = threadIdx.x;
    const int w    = tid >> 5;
    const int lane = tid & 31;
    const int k0   = kc * 32;

    #pragma unroll
    for (int i = 0; i < 16; i++) {
        int m = w * 16 + i;
        sm[m][lane] = x[(size_t)m * 8192 + k0 + lane];
    }
    __syncthreads();

    uint4* dst = g_xpack + (size_t)kc * 512;
    #pragma unroll
    for (int pass = 0; pass < 2; pass++) {
        int g  = tid + pass * 256;
        int lg = g & 31, mb = (g >> 5) & 7, s = g >> 8;
        int m = mb * 16 + (lg >> 2);
        int c = s * 16 + (lg & 3) * 2;
        uint4 v;
        v.x = f2h2(sm[m][c + 1],     sm[m][c]);
        v.y = f2h2(sm[m + 8][c + 1], sm[m + 8][c]);
        v.z = f2h2(sm[m][c + 9],     sm[m][c + 8]);
        v.w = f2h2(sm[m + 8][c + 9], sm[m + 8][c + 8]);
        dst[g] = v;
    }
}

// ---------------- GEMM kernel ----------------
// bid<256: W tile (bid>>2)*128 rows, kq=bid&3.  bid>=256: A tile ((bid-256)>>2)*128, kq.
// warps 0..7 consumers (wm=wid&1: 64 x-rows; nw=(wid>>1)*32: 32 W-rows),
// warps 8,9 producers: 64 lanes LDGSTS W into pad-striped smem + x bulk.
__global__ void __launch_bounds__(320, 2)
lokr_gemm(const float* __restrict__ Wp, const float* __restrict__ Ap,
          float* __restrict__ d_out)
{
    extern __shared__ char smem[];
    const uint32_t sb = smem_u32(smem);
    const int tid  = threadIdx.x;
    const int wid  = tid >> 5;
    const int lane = tid & 31;

    const bool isA = (blockIdx.x >= 256);
    const int  b   = isA ? (blockIdx.x - 256) : blockIdx.x;
    const int  kq  = b & 3;
    const int  row0 = (b >> 2) * W_ROWS;

    if (tid == 0) {
        #pragma unroll
        for (int s = 0; s < STAGES; s++) {
            // full: 64 producer-lane noinc arrives + 1 expect_tx arrive (x bulk)
            MBARRIER_INIT(sb + OFF_FULL  + s * 8, NPROD * 32 + 1);
            MBARRIER_INIT(sb + OFF_EMPTY + s * 8, NCONS);
        }
    }
    __syncthreads();

    if (wid >= NCONS) {
        // ---------------- producers (LDGSTS) ----------------
        const int pl = (wid - NCONS) * 32 + lane;   // 0..63
        const float* src   = isA ? Ap : Wp;
        const float* gbase = src + (size_t)row0 * 8192 + kq * KQ;
        const char*  xsrc  = reinterpret_cast<const char*>(g_xpack) + (size_t)kq * (NK * X_STAGE);

        int es = 0, eph = 1;
        for (int c = 0; c < NK; c++) {
            MBARRIER_WAIT_PARITY(sb + OFF_EMPTY + es * 8, eph);
            uint32_t full = sb + OFF_FULL + es * 8;
            uint32_t st   = sb + SMEM_HDR + es * STAGE_BYTES;
            if (pl == 0) {
                MBARRIER_EXPECT_TX(full, X_STAGE);
                BULK_LOAD(st + W_STAGE, xsrc + (size_t)c * X_STAGE, X_STAGE, full);
            }
            const float* g0 = gbase + c * KC;
            #pragma unroll
            for (int i = 0; i < 32; i++) {
                int g   = i * 64 + pl;        // 0..2047
                int row = g >> 4;             // 0..127
                int cb  = g & 15;             // 16B unit within 256B row chunk
                CP_ASYNC16(st + (uint32_t)(row * W_ROW_B + cb * 16),
                           g0 + (size_t)row * 8192 + cb * 4);
            }
            CP_ASYNC_MBAR_NOINC(full);        // arrives when this lane's copies land
            if (++es == STAGES) { es = 0; eph ^= 1; }
        }
    } else {
        // ---------------- consumers ----------------
        float acc[4][4][4] = {};             // [i: x m16-block][j: W n8-block][frag]
        const int wm = wid & 1;              // x-row half (64 rows)
        const int nw = (wid >> 1) * 32;      // W-row slice (32 rows of 128)
        const int r8 = lane >> 2;
        const int q  = lane & 3;
        const uint32_t q8  = (uint32_t)(q * 8);
        const uint32_t pbW = (uint32_t)((nw + r8) * W_ROW_B);
        const uint32_t xfb = (uint32_t)W_STAGE + (uint32_t)lane * 16;

        int cs = 0, cph = 0;
        for (int c = 0; c < NK; c++) {
            MBARRIER_WAIT_PARITY(sb + OFF_FULL + cs * 8, cph);
            const uint32_t stg = sb + SMEM_HDR + (uint32_t)cs * STAGE_BYTES;
            const uint32_t wb  = stg + pbW + q8;

            #pragma unroll
            for (int s = 0; s < 4; s++) {
                const uint32_t so = (uint32_t)(s * 64);
                // W fragments: 8 LDS.64 fp32 (conflict-free, pad-striped) + cvt
                uint32_t ub[4][2];
                #pragma unroll
                for (int j = 0; j < 4; j++) {
                    float f0, f1, g0, g1;
                    lds64f(wb + (uint32_t)(j * 8 * W_ROW_B) + so,       f0, f1);
                    lds64f(wb + (uint32_t)(j * 8 * W_ROW_B) + so + 32u, g0, g1);
                    ub[j][0] = f2h2(f1, f0);
                    ub[j][1] = f2h2(g1, g0);
                }
                // x fragments: one LDS.128 per m16-block (fp16, prepacked)
                #pragma unroll
                for (int i = 0; i < 4; i++) {
                    uint32_t a0, a1, a2, a3;
                    lds128(stg + xfb + (uint32_t)((s * 8 + wm * 4 + i) << 9), a0, a1, a2, a3);
                    #pragma unroll
                    for (int j = 0; j < 4; j++)
                        mma_f16(acc[i][j], a0, a1, a2, a3, ub[j][0], ub[j][1]);
                }
            }

            __syncwarp();
            if (lane == 0) MBARRIER_ARRIVE(sb + OFF_EMPTY + cs * 8);
            if (++cs == STAGES) { cs = 0; cph ^= 1; }
        }

        // ---------------- epilogue ----------------
        float* ob;
        int stride;
        if (isA) { ob = g_Y2[kq]; stride = 512; }
        else     { ob = kq ? g_P[kq - 1] : d_out; stride = 8192; }
        #pragma unroll
        for (int i = 0; i < 4; i++) {
            #pragma unroll
            for (int j = 0; j < 4; j++) {
                int m = wm * 64 + 16 * i + r8;
                int n = row0 + nw + 8 * j + 2 * q;
                *reinterpret_cast<float2*>(&ob[(size_t)m * stride + n]) =
                    make_float2(acc[i][j][0], acc[i][j][1]);
                *reinterpret_cast<float2*>(&ob[(size_t)(m + 8) * stride + n]) =
                    make_float2(acc[i][j][2], acc[i][j][3]);
            }
        }
    }
}

// ---------------- combine kernel ----------------
__global__ void __launch_bounds__(256)
lokr_combine(const float* __restrict__ lokrB, const float* __restrict__ scalar,
             float* __restrict__ out)
{
    int idx = blockIdx.x * blockDim.x + threadIdx.x;   // float4 id, 0..262143
    int m = idx >> 11;
    int r = idx & 2047;
    int yi = m * 512 + (r >> 2);
    float coef = 2.0f * scalar[0] *
        (g_Y2[0][yi] + g_Y2[1][yi] + g_Y2[2][yi] + g_Y2[3][yi]);

    float4 bv = reinterpret_cast<const float4*>(lokrB)[r & 3];
    float4 o  = reinterpret_cast<float4*>(out)[idx];
    float4 a  = reinterpret_cast<const float4*>(g_P[0])[idx];
    float4 b  = reinterpret_cast<const float4*>(g_P[1])[idx];
    float4 c  = reinterpret_cast<const float4*>(g_P[2])[idx];
    o.x += a.x + b.x + c.x + coef * bv.x;
    o.y += a.y + b.y + c.y + coef * bv.y;
    o.z += a.z + b.z + c.z + coef * bv.z;
    o.w += a.w + b.w + c.w + coef * bv.w;
    reinterpret_cast<float4*>(out)[idx] = o;
}

// ---------------- host ----------------
extern "C" void kernel_launch(void* const* d_in, const int* in_sizes, int n_in,
                              void* d_out, int out_size)
{
    (void)in_sizes; (void)n_in; (void)out_size;
    const float* x  = (const float*)d_in[0];
    const float* W  = (const float*)d_in[1];
    const float* A  = (const float*)d_in[2];
    const float* B  = (const float*)d_in[3];
    const float* sc = (const float*)d_in[4];

    cudaFuncSetAttribute(lokr_gemm, cudaFuncAttributeMaxDynamicSharedMemorySize, SMEM_BYTES);

    prep_x<<<256, 256>>>(x);
    lokr_gemm<<<272, 320, SMEM_BYTES>>>(W, A, (float*)d_out);
    lokr_combine<<<1024, 256>>>(B, sc, (float*)d_out);
}